// round 13
// baseline (speedup 1.0000x reference)
#include <cuda_runtime.h>
#include <math.h>

typedef unsigned long long ull;

// ---------------------------------------------------------------------------
// Scratch (static device globals; no runtime allocation)
// ---------------------------------------------------------------------------
__device__ float g_sb[4 * 8 * 64 * 64 * 64];        // subbands [sub][b][c][64][64]
__device__ float g_co[4 * 8 * 64 * 64 * 64];        // conv outs [sub][b][co][64][64]
__device__ float g_sums[8 * 64 * 4];                // per (b,c,sub) sums
__device__ float g_att[8 * 4 * 4];                  // attention [b][sub][k]
// Winograd U, PRE-DUPLICATED: [b][sub][t][ci][co*2] (each co value stored twice)
__device__ float g_mku[8 * 4 * 16 * 64 * 128];

#define SB_STRIDE  2097152
#define NBC        512
#define UT_STRIDE  8192     // floats per t-slice of U (64 ci x 128)

// Winograd constant tables (B^T row/col selectors on pitch-18 rows, A^T coeffs)
__constant__ int   c_ra[4] = {0 * 18, 1 * 18, 2 * 18, 1 * 18};
__constant__ int   c_rb[4] = {2 * 18, 2 * 18, 1 * 18, 3 * 18};
__constant__ float c_rs[4] = {-1.f, 1.f, -1.f, -1.f};
__constant__ float c_A0[4] = {1.f, 1.f, 1.f, 0.f};   // A^T row 0
__constant__ float c_A1[4] = {0.f, 1.f, -1.f, -1.f}; // A^T row 1

#define FMA2(acc, a, b) asm volatile("fma.rn.f32x2 %0, %1, %2, %0;" \
                                     : "+l"(acc) : "l"(a), "l"(b))
#define DUP2(dst, v)    asm("mov.b64 %0, {%1, %1};" : "=l"(dst) : "f"(v))

// ---------------------------------------------------------------------------
// Kernel 1: Haar DWT fused with per-(b,c) subband sums
// ---------------------------------------------------------------------------
__global__ void dwt_kernel(const float* __restrict__ x) {
    int bc  = blockIdx.x;
    int tid = threadIdx.x;
    int ow  = tid & 63;
    int oh0 = tid >> 6;
    const float* xp = x + (size_t)bc * 128 * 128;

    float s0 = 0.f, s1 = 0.f, s2 = 0.f, s3 = 0.f;
    #pragma unroll 4
    for (int it = 0; it < 16; ++it) {
        int oh = oh0 + it * 4;
        float2 t  = ((const float2*)(xp + (2 * oh)     * 128))[ow];
        float2 bo = ((const float2*)(xp + (2 * oh + 1) * 128))[ow];
        float a = t.x, b_ = t.y, c_ = bo.x, d_ = bo.y;
        float ll = (a + b_ + c_ + d_) * 0.5f;
        float h0 = (a + b_ - c_ - d_) * 0.5f;
        float h1 = (a - b_ + c_ - d_) * 0.5f;
        float hh = (a - b_ - c_ + d_) * 0.5f;
        int o = bc * 4096 + oh * 64 + ow;
        g_sb[0 * SB_STRIDE + o] = ll;
        g_sb[1 * SB_STRIDE + o] = h0;
        g_sb[2 * SB_STRIDE + o] = h1;
        g_sb[3 * SB_STRIDE + o] = hh;
        s0 += ll; s1 += h0; s2 += h1; s3 += hh;
    }

    #pragma unroll
    for (int off = 16; off; off >>= 1) {
        s0 += __shfl_down_sync(0xffffffffu, s0, off);
        s1 += __shfl_down_sync(0xffffffffu, s1, off);
        s2 += __shfl_down_sync(0xffffffffu, s2, off);
        s3 += __shfl_down_sync(0xffffffffu, s3, off);
    }
    __shared__ float red[8][4];
    int warp = tid >> 5, lane = tid & 31;
    if (lane == 0) {
        red[warp][0] = s0; red[warp][1] = s1;
        red[warp][2] = s2; red[warp][3] = s3;
    }
    __syncthreads();
    if (tid < 4) {
        float s = 0.f;
        #pragma unroll
        for (int w = 0; w < 8; ++w) s += red[w][tid];
        g_sums[bc * 4 + tid] = s;
    }
}

// ---------------------------------------------------------------------------
// Kernel 2a: attention logits + softmax
// ---------------------------------------------------------------------------
__global__ void attn_kernel(const float* __restrict__ attn_w,
                            const float* __restrict__ attn_b) {
    int t = threadIdx.x;
    if (t >= 32) return;
    int b = t >> 2, i = t & 3;
    float logits[4];
    #pragma unroll
    for (int k = 0; k < 4; ++k) {
        float acc = 0.f;
        for (int c = 0; c < 64; ++c)
            acc += attn_w[k * 64 + c] * g_sums[(b * 64 + c) * 4 + i];
        logits[k] = acc * (1.0f / 4096.0f) + attn_b[k];
    }
    float m = fmaxf(fmaxf(logits[0], logits[1]), fmaxf(logits[2], logits[3]));
    float e[4]; float s = 0.f;
    #pragma unroll
    for (int k = 0; k < 4; ++k) { e[k] = expf(logits[k] - m); s += e[k]; }
    float inv = 1.0f / s;
    #pragma unroll
    for (int k = 0; k < 4; ++k) g_att[(b * 4 + i) * 4 + k] = e[k] * inv;
}

// ---------------------------------------------------------------------------
// Kernel 2b: mix kernels with attention AND transform to PRE-DUPLICATED U.
//   g_mku[b][i][t][ci][co*2 + {0,1}] = U value (stored twice for f32x2 GEMM)
// ---------------------------------------------------------------------------
__global__ void wino_mix(const float* __restrict__ wt) {
    int cig = blockIdx.x, i = blockIdx.y, b = blockIdx.z;
    int bi = b * 4 + i;
    __shared__ float s[36 * 65];

    int tid = threadIdx.x;
    int co  = tid & 63;
    int cil = tid >> 6;

    float g9[9];
    #pragma unroll
    for (int q = 0; q < 9; ++q) g9[q] = 0.f;

    #pragma unroll
    for (int k = 0; k < 4; ++k) {
        float ak = g_att[bi * 4 + k];
        const float* src = wt + ((size_t)(k * 4 + i) * 64) * 576 + cig * 36;
        __syncthreads();
        for (int idx = tid; idx < 64 * 36; idx += 256) {
            int c = idx / 36;
            int j = idx - c * 36;
            s[j * 65 + c] = src[(size_t)c * 576 + j];
        }
        __syncthreads();
        #pragma unroll
        for (int q = 0; q < 9; ++q)
            g9[q] += ak * s[(cil * 9 + q) * 65 + co];
    }

    // U = G g G^T ; G = [[1,0,0],[.5,.5,.5],[.5,-.5,.5],[0,0,1]]
    float T[4][3];
    #pragma unroll
    for (int c = 0; c < 3; ++c) {
        float a = g9[c], bb = g9[3 + c], cc = g9[6 + c];
        T[0][c] = a;
        T[1][c] = 0.5f * (a + bb + cc);
        T[2][c] = 0.5f * (a - bb + cc);
        T[3][c] = cc;
    }
    float* dst = g_mku + (size_t)bi * 16 * UT_STRIDE
                 + (cig * 4 + cil) * 128 + co * 2;
    #pragma unroll
    for (int r = 0; r < 4; ++r) {
        float u0 = T[r][0], u1b = T[r][1], u2 = T[r][2];
        float U0 = u0;
        float U1 = 0.5f * (u0 + u1b + u2);
        float U2 = 0.5f * (u0 - u1b + u2);
        float U3 = u2;
        *(float2*)(dst + (size_t)(r * 4 + 0) * UT_STRIDE) = make_float2(U0, U0);
        *(float2*)(dst + (size_t)(r * 4 + 1) * UT_STRIDE) = make_float2(U1, U1);
        *(float2*)(dst + (size_t)(r * 4 + 2) * UT_STRIDE) = make_float2(U2, U2);
        *(float2*)(dst + (size_t)(r * 4 + 3) * UT_STRIDE) = make_float2(U3, U3);
    }
}

// ---------------------------------------------------------------------------
// Kernel 3: fused Winograd F(2x2,3x3) conv.  DUP-FREE GEMM + U DOUBLE-BUFFER.
// Block = 256 threads, 64 cout x 16x16 output px (64 wino tiles), one (b,sub).
// ci in 2 chunks of 32. Thread: cog = tid>>4 (4 couts), tq = tid&15 (4 tiles).
// GEMM iter: 2 LDS.128 (dup'd U, 4 cos) + 1 LDS.128 (V, 2 tile-pairs)
//            -> 8 FMA2, zero DUP2.
// U staged into ping-pong smem buffers; next tile staged after current GEMM
// (latency overlapped), ONE sync per jj.
// ---------------------------------------------------------------------------
__global__ void __launch_bounds__(256, 2) wino_conv() {
    extern __shared__ float sm[];
    float* raw_s = sm;                    // 32*324 = 10368 floats
    float* v_s   = sm + 10368;            // 4 * 2048 floats
    float* u_s   = sm + 10368 + 8192;     // 2 buffers x 4096 floats (32 KB)

    int b   = blockIdx.z;
    int sub = blockIdx.y;
    int tb  = blockIdx.x;               // 0..15
    int th0 = (tb >> 2) * 16;           // output row origin (16 rows)
    int tw0 = (tb & 3) * 16;            // output col origin (16 cols)
    int bi  = b * 4 + sub;

    int tid = threadIdx.x;
    int cog = tid >> 4;                 // 0..15 : co4 = cog*4
    int tq  = tid & 15;                 // 0..15 : tiles tq*4 .. tq*4+3

    const float* sbp   = g_sb + (size_t)(sub * 8 + b) * 64 * 4096;
    const float* ubase = g_mku + (size_t)bi * 16 * UT_STRIDE;

    // oacc[co][tp][r][c]: co 0..3, tp = tile-pair 0..1 (lanes = 2 tiles)
    ull oacc[4][2][2][2];
    #pragma unroll
    for (int co = 0; co < 4; ++co)
        #pragma unroll
        for (int tp = 0; tp < 2; ++tp)
            #pragma unroll
            for (int r = 0; r < 2; ++r)
                #pragma unroll
                for (int c = 0; c < 2; ++c) oacc[co][tp][r][c] = 0ull;

    for (int cich = 0; cich < 2; ++cich) {
        int cibase = cich * 32;

        // ---- stage raw halo: 32 ci x 18 x 18 (zero padded) ----
        // (all warps passed the previous jj=3 sync; raw_s free)
        for (int idx = tid; idx < 10368; idx += 256) {
            int ci  = idx / 324;
            int rem = idx - ci * 324;
            int y   = rem / 18;
            int xx  = rem - y * 18;
            int ih  = th0 - 1 + y;
            int iw  = tw0 - 1 + xx;
            float v = 0.f;
            if ((unsigned)ih < 64u && (unsigned)iw < 64u)
                v = sbp[(cibase + ci) * 4096 + ih * 64 + iw];
            raw_s[idx] = v;
        }

        for (int ig = 0; ig < 4; ++ig) {    // B^T row-combination group
            if (ig == 0) __syncthreads();   // raw_s visible

            int   ra = c_ra[ig];
            int   rb = c_rb[ig];
            float rs = c_rs[ig];

            // ---- transform: V[ig][j=0..3] for (32 ci, 64 tiles) ----
            // (v_s free: previous jj=3 sync passed)
            #pragma unroll
            for (int q = 0; q < 8; ++q) {
                int idx = tid + q * 256;    // 2048 cells
                int ci  = idx >> 6;
                int tl  = idx & 63;
                const float* dp =
                    &raw_s[ci * 324 + (tl >> 3) * 36 + (tl & 7) * 2];
                float2 A0 = *(const float2*)(dp + ra);
                float2 A1 = *(const float2*)(dp + ra + 2);
                float2 B0 = *(const float2*)(dp + rb);
                float2 B1 = *(const float2*)(dp + rb + 2);
                float w0 = fmaf(rs, B0.x, A0.x);
                float w1 = fmaf(rs, B0.y, A0.y);
                float w2 = fmaf(rs, B1.x, A1.x);
                float w3 = fmaf(rs, B1.y, A1.y);
                v_s[0 * 2048 + idx] = w0 - w2;
                v_s[1 * 2048 + idx] = w1 + w2;
                v_s[2 * 2048 + idx] = w2 - w1;
                v_s[3 * 2048 + idx] = w1 - w3;
            }

            // ---- stage U(ig,0) into buffer 0 (overlaps transform phase) ----
            {
                const float4* usrc = (const float4*)(
                    ubase + (size_t)(ig * 4) * UT_STRIDE + cibase * 128);
                float4* udst = (float4*)u_s;
                #pragma unroll
                for (int q = 0; q < 4; ++q)
                    udst[tid + q * 256] = usrc[tid + q * 256];
            }
            __syncthreads();                // v_s + u_s[0] visible

            float a0i = c_A0[ig], a1i = c_A1[ig];

            #pragma unroll 1
            for (int jj = 0; jj < 4; ++jj) {
                const float* ucur = u_s + (jj & 1) * 4096;
                const float* vrow = v_s + jj * 2048;

                ull m[4][2];            // [co][tile-pair]
                #pragma unroll
                for (int co = 0; co < 4; ++co)
                    #pragma unroll
                    for (int tp = 0; tp < 2; ++tp) m[co][tp] = 0ull;

                #pragma unroll 4
                for (int ci = 0; ci < 32; ++ci) {
                    const float* ur = ucur + ci * 128 + cog * 8;
                    ulonglong2 ua = *(const ulonglong2*)(ur);      // co0,co1 dup
                    ulonglong2 ub = *(const ulonglong2*)(ur + 4);  // co2,co3 dup
                    ulonglong2 vv =
                        *(const ulonglong2*)(vrow + ci * 64 + tq * 4);
                    FMA2(m[0][0], ua.x, vv.x);
                    FMA2(m[0][1], ua.x, vv.y);
                    FMA2(m[1][0], ua.y, vv.x);
                    FMA2(m[1][1], ua.y, vv.y);
                    FMA2(m[2][0], ub.x, vv.x);
                    FMA2(m[2][1], ub.x, vv.y);
                    FMA2(m[3][0], ub.y, vv.x);
                    FMA2(m[3][1], ub.y, vv.y);
                }

                // fold M into O accumulators with A^T coefficients
                const float CJ0[4] = {1.f, 1.f, 1.f, 0.f};
                const float CJ1[4] = {0.f, 1.f, -1.f, -1.f};
                #pragma unroll
                for (int r = 0; r < 2; ++r) {
                    float rc = r ? a1i : a0i;
                    #pragma unroll
                    for (int c = 0; c < 2; ++c) {
                        float cc = c ? CJ1[jj] : CJ0[jj];
                        if (cc == 0.f) continue;     // compile-time prune
                        float coef = rc * cc;
                        ull cd; DUP2(cd, coef);
                        #pragma unroll
                        for (int co = 0; co < 4; ++co)
                            #pragma unroll
                            for (int tp = 0; tp < 2; ++tp)
                                FMA2(oacc[co][tp][r][c], m[co][tp], cd);
                    }
                }

                // ---- stage U(ig,jj+1) into the other buffer ----
                if (jj < 3) {
                    const float4* usrc = (const float4*)(
                        ubase + (size_t)(ig * 4 + jj + 1) * UT_STRIDE
                        + cibase * 128);
                    float4* udst = (float4*)(u_s + ((jj + 1) & 1) * 4096);
                    #pragma unroll
                    for (int q = 0; q < 4; ++q)
                        udst[tid + q * 256] = usrc[tid + q * 256];
                }
                __syncthreads();        // staged buffer visible; frees v_s[jj]
            }
        }
    }

    // ---- writeback: tile-pair lanes unpack to x-adjacent pixels -> float4 ----
    float* outp = g_co + (size_t)(sub * 8 + b) * 64 * 4096;
    int co4 = cog * 4;
    int oy  = th0 + (tq >> 1) * 2;
    int ox0 = tw0 + (tq & 1) * 8;
    #pragma unroll
    for (int co = 0; co < 4; ++co) {
        #pragma unroll
        for (int r = 0; r < 2; ++r) {
            float t0c0, t1c0, t0c1, t1c1, t2c0, t3c0, t2c1, t3c1;
            asm("mov.b64 {%0, %1}, %2;" : "=f"(t0c0), "=f"(t1c0)
                : "l"(oacc[co][0][r][0]));
            asm("mov.b64 {%0, %1}, %2;" : "=f"(t0c1), "=f"(t1c1)
                : "l"(oacc[co][0][r][1]));
            asm("mov.b64 {%0, %1}, %2;" : "=f"(t2c0), "=f"(t3c0)
                : "l"(oacc[co][1][r][0]));
            asm("mov.b64 {%0, %1}, %2;" : "=f"(t2c1), "=f"(t3c1)
                : "l"(oacc[co][1][r][1]));
            float* op = outp + (size_t)(co4 + co) * 4096
                        + (size_t)(oy + r) * 64 + ox0;
            *(float4*)(op)     = make_float4(t0c0, t0c1, t1c0, t1c1);
            *(float4*)(op + 4) = make_float4(t2c0, t2c1, t3c0, t3c1);
        }
    }
}

// ---------------------------------------------------------------------------
// Kernel 4: inverse Haar DWT -> final output
// ---------------------------------------------------------------------------
__global__ void idwt_kernel(float* __restrict__ out) {
    int idx = blockIdx.x * blockDim.x + threadIdx.x;
    if (idx >= SB_STRIDE) return;
    int w  = idx & 63;
    int h  = (idx >> 6) & 63;
    int bc = idx >> 12;

    float ll = g_co[idx];
    float h0 = g_co[SB_STRIDE + idx];
    float h1 = g_co[2 * SB_STRIDE + idx];
    float hh = g_co[3 * SB_STRIDE + idx];

    float a  = (ll + h0 + h1 + hh) * 0.5f;
    float b_ = (ll + h0 - h1 - hh) * 0.5f;
    float c_ = (ll - h0 + h1 - hh) * 0.5f;
    float d_ = (ll - h0 - h1 + hh) * 0.5f;

    float2* top = (float2*)(out + ((size_t)bc * 128 + 2 * h) * 128);
    float2* bot = (float2*)(out + ((size_t)bc * 128 + 2 * h + 1) * 128);
    top[w] = make_float2(a, b_);
    bot[w] = make_float2(c_, d_);
}

// ---------------------------------------------------------------------------
// Launch
// ---------------------------------------------------------------------------
extern "C" void kernel_launch(void* const* d_in, const int* in_sizes, int n_in,
                              void* d_out, int out_size) {
    const float* x  = (const float*)d_in[0];
    const float* wt = (const float*)d_in[1];
    const float* aw = (const float*)d_in[2];
    const float* ab = (const float*)d_in[3];
    float* out = (float*)d_out;

    static const int kConvSmem = (10368 + 4 * 2048 + 2 * 4096) * 4;  // 107008 B
    cudaFuncSetAttribute(wino_conv,
                         cudaFuncAttributeMaxDynamicSharedMemorySize, kConvSmem);

    dwt_kernel<<<NBC, 256>>>(x);
    attn_kernel<<<1, 32>>>(aw, ab);
    wino_mix<<<dim3(16, 4, 8), 256>>>(wt);
    wino_conv<<<dim3(16, 4, 8), 256, kConvSmem>>>();
    idwt_kernel<<<8192, 256>>>(out);
}

// round 14
// speedup vs baseline: 1.1662x; 1.1662x over previous
#include <cuda_runtime.h>
#include <math.h>

typedef unsigned long long ull;

// ---------------------------------------------------------------------------
// Scratch (static device globals; no runtime allocation)
// ---------------------------------------------------------------------------
__device__ float g_sb[4 * 8 * 64 * 64 * 64];        // subbands [sub][b][c][64][64]
__device__ float g_co[4 * 8 * 64 * 64 * 64];        // conv outs [sub][b][co][64][64]
__device__ float g_sums[8 * 64 * 4];                // per (b,c,sub) sums
__device__ float g_att[8 * 4 * 4];                  // attention [b][sub][k]
__device__ float g_mku[8 * 4 * 16 * 64 * 64];       // Winograd U [b][sub][t][ci][co]

#define SB_STRIDE  2097152
#define NBC        512

// Winograd constant tables (B^T row/col selectors on pitch-18 rows, A^T coeffs)
__constant__ int   c_ra[4] = {0 * 18, 1 * 18, 2 * 18, 1 * 18};
__constant__ int   c_rb[4] = {2 * 18, 2 * 18, 1 * 18, 3 * 18};
__constant__ float c_rs[4] = {-1.f, 1.f, -1.f, -1.f};
__constant__ float c_A0[4] = {1.f, 1.f, 1.f, 0.f};   // A^T row 0
__constant__ float c_A1[4] = {0.f, 1.f, -1.f, -1.f}; // A^T row 1

#define FMA2(acc, a, b) asm volatile("fma.rn.f32x2 %0, %1, %2, %0;" \
                                     : "+l"(acc) : "l"(a), "l"(b))
#define DUP2(dst, v)    asm("mov.b64 %0, {%1, %1};" : "=l"(dst) : "f"(v))

// ---------------------------------------------------------------------------
// Kernel 1: Haar DWT fused with per-(b,c) subband sums
// ---------------------------------------------------------------------------
__global__ void dwt_kernel(const float* __restrict__ x) {
    int bc  = blockIdx.x;
    int tid = threadIdx.x;
    int ow  = tid & 63;
    int oh0 = tid >> 6;
    const float* xp = x + (size_t)bc * 128 * 128;

    float s0 = 0.f, s1 = 0.f, s2 = 0.f, s3 = 0.f;
    #pragma unroll 4
    for (int it = 0; it < 16; ++it) {
        int oh = oh0 + it * 4;
        float2 t  = ((const float2*)(xp + (2 * oh)     * 128))[ow];
        float2 bo = ((const float2*)(xp + (2 * oh + 1) * 128))[ow];
        float a = t.x, b_ = t.y, c_ = bo.x, d_ = bo.y;
        float ll = (a + b_ + c_ + d_) * 0.5f;
        float h0 = (a + b_ - c_ - d_) * 0.5f;
        float h1 = (a - b_ + c_ - d_) * 0.5f;
        float hh = (a - b_ - c_ + d_) * 0.5f;
        int o = bc * 4096 + oh * 64 + ow;
        g_sb[0 * SB_STRIDE + o] = ll;
        g_sb[1 * SB_STRIDE + o] = h0;
        g_sb[2 * SB_STRIDE + o] = h1;
        g_sb[3 * SB_STRIDE + o] = hh;
        s0 += ll; s1 += h0; s2 += h1; s3 += hh;
    }

    #pragma unroll
    for (int off = 16; off; off >>= 1) {
        s0 += __shfl_down_sync(0xffffffffu, s0, off);
        s1 += __shfl_down_sync(0xffffffffu, s1, off);
        s2 += __shfl_down_sync(0xffffffffu, s2, off);
        s3 += __shfl_down_sync(0xffffffffu, s3, off);
    }
    __shared__ float red[8][4];
    int warp = tid >> 5, lane = tid & 31;
    if (lane == 0) {
        red[warp][0] = s0; red[warp][1] = s1;
        red[warp][2] = s2; red[warp][3] = s3;
    }
    __syncthreads();
    if (tid < 4) {
        float s = 0.f;
        #pragma unroll
        for (int w = 0; w < 8; ++w) s += red[w][tid];
        g_sums[bc * 4 + tid] = s;
    }
}

// ---------------------------------------------------------------------------
// Kernel 2a: attention logits + softmax
// ---------------------------------------------------------------------------
__global__ void attn_kernel(const float* __restrict__ attn_w,
                            const float* __restrict__ attn_b) {
    int t = threadIdx.x;
    if (t >= 32) return;
    int b = t >> 2, i = t & 3;
    float logits[4];
    #pragma unroll
    for (int k = 0; k < 4; ++k) {
        float acc = 0.f;
        for (int c = 0; c < 64; ++c)
            acc += attn_w[k * 64 + c] * g_sums[(b * 64 + c) * 4 + i];
        logits[k] = acc * (1.0f / 4096.0f) + attn_b[k];
    }
    float m = fmaxf(fmaxf(logits[0], logits[1]), fmaxf(logits[2], logits[3]));
    float e[4]; float s = 0.f;
    #pragma unroll
    for (int k = 0; k < 4; ++k) { e[k] = expf(logits[k] - m); s += e[k]; }
    float inv = 1.0f / s;
    #pragma unroll
    for (int k = 0; k < 4; ++k) g_att[(b * 4 + i) * 4 + k] = e[k] * inv;
}

// ---------------------------------------------------------------------------
// Kernel 2b: mix kernels with attention AND transform to Winograd U.
// (R11 layout: [b][sub][t][ci][co], single floats)
// ---------------------------------------------------------------------------
__global__ void wino_mix(const float* __restrict__ wt) {
    int cig = blockIdx.x, i = blockIdx.y, b = blockIdx.z;
    int bi = b * 4 + i;
    __shared__ float s[36 * 65];

    int tid = threadIdx.x;
    int co  = tid & 63;
    int cil = tid >> 6;

    float g9[9];
    #pragma unroll
    for (int q = 0; q < 9; ++q) g9[q] = 0.f;

    #pragma unroll
    for (int k = 0; k < 4; ++k) {
        float ak = g_att[bi * 4 + k];
        const float* src = wt + ((size_t)(k * 4 + i) * 64) * 576 + cig * 36;
        __syncthreads();
        for (int idx = tid; idx < 64 * 36; idx += 256) {
            int c = idx / 36;
            int j = idx - c * 36;
            s[j * 65 + c] = src[(size_t)c * 576 + j];
        }
        __syncthreads();
        #pragma unroll
        for (int q = 0; q < 9; ++q)
            g9[q] += ak * s[(cil * 9 + q) * 65 + co];
    }

    // U = G g G^T ; G = [[1,0,0],[.5,.5,.5],[.5,-.5,.5],[0,0,1]]
    float T[4][3];
    #pragma unroll
    for (int c = 0; c < 3; ++c) {
        float a = g9[c], bb = g9[3 + c], cc = g9[6 + c];
        T[0][c] = a;
        T[1][c] = 0.5f * (a + bb + cc);
        T[2][c] = 0.5f * (a - bb + cc);
        T[3][c] = cc;
    }
    float* dst = g_mku + ((size_t)bi * 16) * 4096 + (cig * 4 + cil) * 64 + co;
    #pragma unroll
    for (int r = 0; r < 4; ++r) {
        float u0 = T[r][0], u1b = T[r][1], u2 = T[r][2];
        float U0 = u0;
        float U1 = 0.5f * (u0 + u1b + u2);
        float U2 = 0.5f * (u0 - u1b + u2);
        float U3 = u2;
        dst[(r * 4 + 0) * 4096] = U0;
        dst[(r * 4 + 1) * 4096] = U1;
        dst[(r * 4 + 2) * 4096] = U2;
        dst[(r * 4 + 3) * 4096] = U3;
    }
}

// ---------------------------------------------------------------------------
// Kernel 3: fused Winograd F(2x2,3x3) conv.  R11 GEMM + QUAD-BUFFERED U.
// Block = 256 threads, 64 cout x 16x16 output px (64 wino tiles), one (b,sub).
// ci in 2 chunks of 32. Thread: cog = tid>>4 (4 couts), tq = tid&15 (4 tiles).
// Per ig: transform V, stage ALL FOUR U(ig,jj) tiles, ONE sync, then 4 GEMMs
// run sync-free (128 iters), one sync at ig end.  18 syncs total (was 42).
// ---------------------------------------------------------------------------
__global__ void __launch_bounds__(256, 2) wino_conv() {
    extern __shared__ float sm[];
    float* raw_s = sm;                    // 32*324 = 10368 floats
    float* v_s   = sm + 10368;            // 4 * 2048 floats
    float* u_s   = sm + 10368 + 8192;     // 4 buffers x 2048 floats (32 KB)

    int b   = blockIdx.z;
    int sub = blockIdx.y;
    int tb  = blockIdx.x;               // 0..15
    int th0 = (tb >> 2) * 16;           // output row origin (16 rows)
    int tw0 = (tb & 3) * 16;            // output col origin (16 cols)
    int bi  = b * 4 + sub;

    int tid = threadIdx.x;
    int cog = tid >> 4;                 // 0..15 : co4 = cog*4
    int tq  = tid & 15;                 // 0..15 : tiles tq*4 .. tq*4+3

    const float* sbp   = g_sb + (size_t)(sub * 8 + b) * 64 * 4096;
    const float* ubase = g_mku + (size_t)bi * 16 * 4096;

    // oacc[p][l][r][c]: p = co-pair (0,1), l = tile 0..3, (r,c) = output px
    ull oacc[2][4][2][2];
    #pragma unroll
    for (int p = 0; p < 2; ++p)
        #pragma unroll
        for (int l = 0; l < 4; ++l)
            #pragma unroll
            for (int r = 0; r < 2; ++r)
                #pragma unroll
                for (int c = 0; c < 2; ++c) oacc[p][l][r][c] = 0ull;

    for (int cich = 0; cich < 2; ++cich) {
        int cibase = cich * 32;

        // ---- stage raw halo: 32 ci x 18 x 18 (zero padded) ----
        // (safe: all warps passed the previous ig-end sync, raw_s free)
        for (int idx = tid; idx < 10368; idx += 256) {
            int ci  = idx / 324;
            int rem = idx - ci * 324;
            int y   = rem / 18;
            int xx  = rem - y * 18;
            int ih  = th0 - 1 + y;
            int iw  = tw0 - 1 + xx;
            float v = 0.f;
            if ((unsigned)ih < 64u && (unsigned)iw < 64u)
                v = sbp[(cibase + ci) * 4096 + ih * 64 + iw];
            raw_s[idx] = v;
        }
        __syncthreads();                // raw_s visible

        for (int ig = 0; ig < 4; ++ig) {    // B^T row-combination group
            int   ra = c_ra[ig];
            int   rb = c_rb[ig];
            float rs = c_rs[ig];

            // ---- transform: V[ig][j=0..3] for (32 ci, 64 tiles) ----
            // (v_s/u_s free: previous ig-end sync passed)
            #pragma unroll
            for (int q = 0; q < 8; ++q) {
                int idx = tid + q * 256;    // 2048 cells
                int ci  = idx >> 6;
                int tl  = idx & 63;
                const float* dp =
                    &raw_s[ci * 324 + (tl >> 3) * 36 + (tl & 7) * 2];
                float2 A0 = *(const float2*)(dp + ra);
                float2 A1 = *(const float2*)(dp + ra + 2);
                float2 B0 = *(const float2*)(dp + rb);
                float2 B1 = *(const float2*)(dp + rb + 2);
                float w0 = fmaf(rs, B0.x, A0.x);
                float w1 = fmaf(rs, B0.y, A0.y);
                float w2 = fmaf(rs, B1.x, A1.x);
                float w3 = fmaf(rs, B1.y, A1.y);
                v_s[0 * 2048 + idx] = w0 - w2;
                v_s[1 * 2048 + idx] = w1 + w2;
                v_s[2 * 2048 + idx] = w2 - w1;
                v_s[3 * 2048 + idx] = w1 - w3;
            }

            // ---- stage U(ig, 0..3): 4 x 2048 floats, coalesced float4 ----
            #pragma unroll
            for (int jj4 = 0; jj4 < 4; ++jj4) {
                const float4* usrc = (const float4*)(
                    ubase + (size_t)(ig * 4 + jj4) * 4096 + cibase * 64);
                float4* udst = (float4*)(u_s + jj4 * 2048);
                udst[tid]       = usrc[tid];
                udst[tid + 256] = usrc[tid + 256];
            }
            __syncthreads();            // v_s + all 4 u_s buffers visible

            float a0i = c_A0[ig], a1i = c_A1[ig];

            #pragma unroll 1
            for (int jj = 0; jj < 4; ++jj) {    // SYNC-FREE GEMM stretch
                const ulonglong2* up =
                    (const ulonglong2*)(u_s + jj * 2048) + cog;
                const float4* vp = (const float4*)(v_s + jj * 2048) + tq;

                ull m[2][4];            // [co-pair][tile]
                #pragma unroll
                for (int p = 0; p < 2; ++p)
                    #pragma unroll
                    for (int l = 0; l < 4; ++l) m[p][l] = 0ull;

                #pragma unroll 4
                for (int ci = 0; ci < 32; ++ci) {
                    ulonglong2 u = up[ci * 16];     // 64 floats/ci = 16 u2
                    float4 v4 = vp[ci * 16];        // 64 floats/ci = 16 f4
                    ull vd0, vd1, vd2, vd3;
                    DUP2(vd0, v4.x); DUP2(vd1, v4.y);
                    DUP2(vd2, v4.z); DUP2(vd3, v4.w);
                    FMA2(m[0][0], u.x, vd0);
                    FMA2(m[0][1], u.x, vd1);
                    FMA2(m[0][2], u.x, vd2);
                    FMA2(m[0][3], u.x, vd3);
                    FMA2(m[1][0], u.y, vd0);
                    FMA2(m[1][1], u.y, vd1);
                    FMA2(m[1][2], u.y, vd2);
                    FMA2(m[1][3], u.y, vd3);
                }

                // fold M into O accumulators with A^T coefficients
                const float CJ0[4] = {1.f, 1.f, 1.f, 0.f};
                const float CJ1[4] = {0.f, 1.f, -1.f, -1.f};
                #pragma unroll
                for (int r = 0; r < 2; ++r) {
                    float rc = r ? a1i : a0i;
                    #pragma unroll
                    for (int c = 0; c < 2; ++c) {
                        float cc = c ? CJ1[jj] : CJ0[jj];
                        if (cc == 0.f) continue;     // compile-time prune
                        float coef = rc * cc;
                        ull cd; DUP2(cd, coef);
                        #pragma unroll
                        for (int p = 0; p < 2; ++p)
                            #pragma unroll
                            for (int l = 0; l < 4; ++l)
                                FMA2(oacc[p][l][r][c], m[p][l], cd);
                    }
                }
            }
            __syncthreads();            // all GEMM reads done: v_s/u_s/raw_s
                                        // free for next ig / next ci chunk
        }
    }

    // ---- writeback: unpack co pairs, store float2 per output row ----
    float* outp = g_co + (size_t)(sub * 8 + b) * 64 * 4096;
    int co4 = cog * 4;
    #pragma unroll
    for (int l = 0; l < 4; ++l) {
        int tl = tq * 4 + l;
        int oy = th0 + (tl >> 3) * 2;
        int ox = tw0 + (tl & 7) * 2;
        #pragma unroll
        for (int p = 0; p < 2; ++p) {
            #pragma unroll
            for (int r = 0; r < 2; ++r) {
                float lo0, hi0, lo1, hi1;
                asm("mov.b64 {%0, %1}, %2;" : "=f"(lo0), "=f"(hi0)
                    : "l"(oacc[p][l][r][0]));
                asm("mov.b64 {%0, %1}, %2;" : "=f"(lo1), "=f"(hi1)
                    : "l"(oacc[p][l][r][1]));
                size_t off = (size_t)(oy + r) * 64 + ox;
                *(float2*)(outp + (size_t)(co4 + 2 * p)     * 4096 + off) =
                    make_float2(lo0, lo1);
                *(float2*)(outp + (size_t)(co4 + 2 * p + 1) * 4096 + off) =
                    make_float2(hi0, hi1);
            }
        }
    }
}

// ---------------------------------------------------------------------------
// Kernel 4: inverse Haar DWT -> final output
// ---------------------------------------------------------------------------
__global__ void idwt_kernel(float* __restrict__ out) {
    int idx = blockIdx.x * blockDim.x + threadIdx.x;
    if (idx >= SB_STRIDE) return;
    int w  = idx & 63;
    int h  = (idx >> 6) & 63;
    int bc = idx >> 12;

    float ll = g_co[idx];
    float h0 = g_co[SB_STRIDE + idx];
    float h1 = g_co[2 * SB_STRIDE + idx];
    float hh = g_co[3 * SB_STRIDE + idx];

    float a  = (ll + h0 + h1 + hh) * 0.5f;
    float b_ = (ll + h0 - h1 - hh) * 0.5f;
    float c_ = (ll - h0 + h1 - hh) * 0.5f;
    float d_ = (ll - h0 - h1 + hh) * 0.5f;

    float2* top = (float2*)(out + ((size_t)bc * 128 + 2 * h) * 128);
    float2* bot = (float2*)(out + ((size_t)bc * 128 + 2 * h + 1) * 128);
    top[w] = make_float2(a, b_);
    bot[w] = make_float2(c_, d_);
}

// ---------------------------------------------------------------------------
// Launch
// ---------------------------------------------------------------------------
extern "C" void kernel_launch(void* const* d_in, const int* in_sizes, int n_in,
                              void* d_out, int out_size) {
    const float* x  = (const float*)d_in[0];
    const float* wt = (const float*)d_in[1];
    const float* aw = (const float*)d_in[2];
    const float* ab = (const float*)d_in[3];
    float* out = (float*)d_out;

    static const int kConvSmem = (10368 + 4 * 2048 + 4 * 2048) * 4;  // 107008 B
    cudaFuncSetAttribute(wino_conv,
                         cudaFuncAttributeMaxDynamicSharedMemorySize, kConvSmem);

    dwt_kernel<<<NBC, 256>>>(x);
    attn_kernel<<<1, 32>>>(aw, ab);
    wino_mix<<<dim3(16, 4, 8), 256>>>(wt);
    wino_conv<<<dim3(16, 4, 8), 256, kConvSmem>>>();
    idwt_kernel<<<8192, 256>>>(out);
}

// round 15
// speedup vs baseline: 1.6124x; 1.3827x over previous
#include <cuda_runtime.h>
#include <math.h>

typedef unsigned long long ull;

// ---------------------------------------------------------------------------
// Scratch (static device globals; no runtime allocation)
// ---------------------------------------------------------------------------
__device__ float g_sb[4 * 8 * 64 * 64 * 64];        // subbands [sub][b][c][64][64]
__device__ float g_co[4 * 8 * 64 * 64 * 64];        // conv outs [sub][b][co][64][64]
__device__ float g_sums[8 * 64 * 4];                // per (b,c,sub) sums
__device__ float g_att[8 * 4 * 4];                  // attention [b][sub][k]
__device__ float g_mku[8 * 4 * 16 * 64 * 64];       // Winograd U [b][sub][t][ci][co]

#define SB_STRIDE  2097152
#define NBC        512

// Winograd constant tables (B^T row/col selectors on pitch-18 rows, A^T coeffs)
__constant__ int   c_ra[4] = {0 * 18, 1 * 18, 2 * 18, 1 * 18};
__constant__ int   c_rb[4] = {2 * 18, 2 * 18, 1 * 18, 3 * 18};
__constant__ float c_rs[4] = {-1.f, 1.f, -1.f, -1.f};
__constant__ float c_A0[4] = {1.f, 1.f, 1.f, 0.f};   // A^T row 0
__constant__ float c_A1[4] = {0.f, 1.f, -1.f, -1.f}; // A^T row 1

#define CVT_TF32(d, s) asm("cvt.rna.tf32.f32 %0, %1;" : "=r"(d) : "f"(s))

#define MMA_TF32(d, a, b)                                                    \
    asm volatile(                                                            \
        "mma.sync.aligned.m16n8k8.row.col.f32.tf32.tf32.f32 "                \
        "{%0,%1,%2,%3}, {%4,%5,%6,%7}, {%8,%9}, {%0,%1,%2,%3};"              \
        : "+f"((d)[0]), "+f"((d)[1]), "+f"((d)[2]), "+f"((d)[3])             \
        : "r"((a)[0]), "r"((a)[1]), "r"((a)[2]), "r"((a)[3]),                \
          "r"((b)[0]), "r"((b)[1]))

// ---------------------------------------------------------------------------
// Kernel 1: Haar DWT fused with per-(b,c) subband sums
// ---------------------------------------------------------------------------
__global__ void dwt_kernel(const float* __restrict__ x) {
    int bc  = blockIdx.x;
    int tid = threadIdx.x;
    int ow  = tid & 63;
    int oh0 = tid >> 6;
    const float* xp = x + (size_t)bc * 128 * 128;

    float s0 = 0.f, s1 = 0.f, s2 = 0.f, s3 = 0.f;
    #pragma unroll 4
    for (int it = 0; it < 16; ++it) {
        int oh = oh0 + it * 4;
        float2 t  = ((const float2*)(xp + (2 * oh)     * 128))[ow];
        float2 bo = ((const float2*)(xp + (2 * oh + 1) * 128))[ow];
        float a = t.x, b_ = t.y, c_ = bo.x, d_ = bo.y;
        float ll = (a + b_ + c_ + d_) * 0.5f;
        float h0 = (a + b_ - c_ - d_) * 0.5f;
        float h1 = (a - b_ + c_ - d_) * 0.5f;
        float hh = (a - b_ - c_ + d_) * 0.5f;
        int o = bc * 4096 + oh * 64 + ow;
        g_sb[0 * SB_STRIDE + o] = ll;
        g_sb[1 * SB_STRIDE + o] = h0;
        g_sb[2 * SB_STRIDE + o] = h1;
        g_sb[3 * SB_STRIDE + o] = hh;
        s0 += ll; s1 += h0; s2 += h1; s3 += hh;
    }

    #pragma unroll
    for (int off = 16; off; off >>= 1) {
        s0 += __shfl_down_sync(0xffffffffu, s0, off);
        s1 += __shfl_down_sync(0xffffffffu, s1, off);
        s2 += __shfl_down_sync(0xffffffffu, s2, off);
        s3 += __shfl_down_sync(0xffffffffu, s3, off);
    }
    __shared__ float red[8][4];
    int warp = tid >> 5, lane = tid & 31;
    if (lane == 0) {
        red[warp][0] = s0; red[warp][1] = s1;
        red[warp][2] = s2; red[warp][3] = s3;
    }
    __syncthreads();
    if (tid < 4) {
        float s = 0.f;
        #pragma unroll
        for (int w = 0; w < 8; ++w) s += red[w][tid];
        g_sums[bc * 4 + tid] = s;
    }
}

// ---------------------------------------------------------------------------
// Kernel 2a: attention logits + softmax
// ---------------------------------------------------------------------------
__global__ void attn_kernel(const float* __restrict__ attn_w,
                            const float* __restrict__ attn_b) {
    int t = threadIdx.x;
    if (t >= 32) return;
    int b = t >> 2, i = t & 3;
    float logits[4];
    #pragma unroll
    for (int k = 0; k < 4; ++k) {
        float acc = 0.f;
        for (int c = 0; c < 64; ++c)
            acc += attn_w[k * 64 + c] * g_sums[(b * 64 + c) * 4 + i];
        logits[k] = acc * (1.0f / 4096.0f) + attn_b[k];
    }
    float m = fmaxf(fmaxf(logits[0], logits[1]), fmaxf(logits[2], logits[3]));
    float e[4]; float s = 0.f;
    #pragma unroll
    for (int k = 0; k < 4; ++k) { e[k] = expf(logits[k] - m); s += e[k]; }
    float inv = 1.0f / s;
    #pragma unroll
    for (int k = 0; k < 4; ++k) g_att[(b * 4 + i) * 4 + k] = e[k] * inv;
}

// ---------------------------------------------------------------------------
// Kernel 2b: mix kernels with attention AND transform to Winograd U.
// (layout: [b][sub][t][ci][co], co contiguous)
// ---------------------------------------------------------------------------
__global__ void wino_mix(const float* __restrict__ wt) {
    int cig = blockIdx.x, i = blockIdx.y, b = blockIdx.z;
    int bi = b * 4 + i;
    __shared__ float s[36 * 65];

    int tid = threadIdx.x;
    int co  = tid & 63;
    int cil = tid >> 6;

    float g9[9];
    #pragma unroll
    for (int q = 0; q < 9; ++q) g9[q] = 0.f;

    #pragma unroll
    for (int k = 0; k < 4; ++k) {
        float ak = g_att[bi * 4 + k];
        const float* src = wt + ((size_t)(k * 4 + i) * 64) * 576 + cig * 36;
        __syncthreads();
        for (int idx = tid; idx < 64 * 36; idx += 256) {
            int c = idx / 36;
            int j = idx - c * 36;
            s[j * 65 + c] = src[(size_t)c * 576 + j];
        }
        __syncthreads();
        #pragma unroll
        for (int q = 0; q < 9; ++q)
            g9[q] += ak * s[(cil * 9 + q) * 65 + co];
    }

    // U = G g G^T ; G = [[1,0,0],[.5,.5,.5],[.5,-.5,.5],[0,0,1]]
    float T[4][3];
    #pragma unroll
    for (int c = 0; c < 3; ++c) {
        float a = g9[c], bb = g9[3 + c], cc = g9[6 + c];
        T[0][c] = a;
        T[1][c] = 0.5f * (a + bb + cc);
        T[2][c] = 0.5f * (a - bb + cc);
        T[3][c] = cc;
    }
    float* dst = g_mku + ((size_t)bi * 16) * 4096 + (cig * 4 + cil) * 64 + co;
    #pragma unroll
    for (int r = 0; r < 4; ++r) {
        float u0 = T[r][0], u1b = T[r][1], u2 = T[r][2];
        float U0 = u0;
        float U1 = 0.5f * (u0 + u1b + u2);
        float U2 = 0.5f * (u0 - u1b + u2);
        float U3 = u2;
        dst[(r * 4 + 0) * 4096] = U0;
        dst[(r * 4 + 1) * 4096] = U1;
        dst[(r * 4 + 2) * 4096] = U2;
        dst[(r * 4 + 3) * 4096] = U3;
    }
}

// ---------------------------------------------------------------------------
// Kernel 3: fused Winograd F(2x2,3x3) conv — TENSOR CORE (tf32 mma.sync).
// Block = 256 threads (8 warps), 64 cout x 16x16 px (64 wino tiles), 1 (b,sub).
// ci in 2 chunks of 32.  GEMM per (ig,jj): C[64co x 64t] = U^T V via
// mma.m16n8k8: warp w -> m-tile (w&3: 16 co), n-tiles (w>>2)*4+{0..3} (8 t ea).
// A-frags: __ldg direct from g_mku (L1/L2-hot t-slices, 16 loads MLP up front).
// B-frags: LDS from v_s pitch 72 (72%32==8 -> banks 8*tig+gid, conflict-free).
// M folded into fp32 oacc with A^T coeffs.  18 syncs total (R13 schedule).
// ---------------------------------------------------------------------------
__global__ void __launch_bounds__(256, 2) wino_conv() {
    extern __shared__ float sm[];
    float* raw_s = sm;                    // 32*324 = 10368 floats
    float* v_s   = sm + 10368;            // 4 jj x (32 ci x 72) = 9216 floats

    int b   = blockIdx.z;
    int sub = blockIdx.y;
    int tb  = blockIdx.x;               // 0..15
    int th0 = (tb >> 2) * 16;           // output row origin (16 rows)
    int tw0 = (tb & 3) * 16;            // output col origin (16 cols)
    int bi  = b * 4 + sub;

    int tid  = threadIdx.x;
    int w    = tid >> 5;
    int lane = tid & 31;
    int gid  = lane >> 2;               // 0..7
    int tig  = lane & 3;                // 0..3
    int mi   = w & 3;                   // m-tile: co range mi*16..+16
    int ng   = w >> 1 >> 1;             // w>>2: n-group (0 or 1)
    int co0  = mi * 16;

    const float* sbp   = g_sb  + (size_t)(sub * 8 + b) * 64 * 4096;
    const float* ubase = g_mku + (size_t)bi * 16 * 4096;

    // oacc[rc = r*2+c][nq][creg]: 4 x 4 x 4 fp32
    float oacc[4][4][4];
    #pragma unroll
    for (int rc = 0; rc < 4; ++rc)
        #pragma unroll
        for (int nq = 0; nq < 4; ++nq)
            #pragma unroll
            for (int q = 0; q < 4; ++q) oacc[rc][nq][q] = 0.f;

    for (int cich = 0; cich < 2; ++cich) {
        int cibase = cich * 32;

        // ---- stage raw halo: 32 ci x 18 x 18 (zero padded) ----
        for (int idx = tid; idx < 10368; idx += 256) {
            int ci  = idx / 324;
            int rem = idx - ci * 324;
            int y   = rem / 18;
            int xx  = rem - y * 18;
            int ih  = th0 - 1 + y;
            int iw  = tw0 - 1 + xx;
            float v = 0.f;
            if ((unsigned)ih < 64u && (unsigned)iw < 64u)
                v = sbp[(cibase + ci) * 4096 + ih * 64 + iw];
            raw_s[idx] = v;
        }
        __syncthreads();                // raw_s visible

        for (int ig = 0; ig < 4; ++ig) {
            int   ra = c_ra[ig];
            int   rb = c_rb[ig];
            float rs = c_rs[ig];

            // ---- transform: V[ig][jj=0..3] for (32 ci, 64 tiles) ----
            #pragma unroll
            for (int q = 0; q < 8; ++q) {
                int idx = tid + q * 256;    // 2048 cells
                int ci  = idx >> 6;
                int tl  = idx & 63;
                const float* dp =
                    &raw_s[ci * 324 + (tl >> 3) * 36 + (tl & 7) * 2];
                float2 A0 = *(const float2*)(dp + ra);
                float2 A1 = *(const float2*)(dp + ra + 2);
                float2 B0 = *(const float2*)(dp + rb);
                float2 B1 = *(const float2*)(dp + rb + 2);
                float w0 = fmaf(rs, B0.x, A0.x);
                float w1 = fmaf(rs, B0.y, A0.y);
                float w2 = fmaf(rs, B1.x, A1.x);
                float w3 = fmaf(rs, B1.y, A1.y);
                int off = ci * 72 + tl;
                v_s[0 * 2304 + off] = w0 - w2;
                v_s[1 * 2304 + off] = w1 + w2;
                v_s[2 * 2304 + off] = w2 - w1;
                v_s[3 * 2304 + off] = w1 - w3;
            }
            __syncthreads();            // v_s visible

            float a0i = c_A0[ig], a1i = c_A1[ig];

            #pragma unroll 1
            for (int jj = 0; jj < 4; ++jj) {    // sync-free GEMM stretch
                const float* vb = v_s + jj * 2304;
                const float* gu = ubase + (size_t)(ig * 4 + jj) * 4096
                                  + cibase * 64;

                // ---- A fragments: 16 upfront LDGs (MLP 16) + cvt ----
                unsigned afr[4][4];
                #pragma unroll
                for (int ks = 0; ks < 4; ++ks) {
                    const float* ua = gu + (ks * 8 + tig) * 64 + co0 + gid;
                    float f0 = __ldg(ua);
                    float f1 = __ldg(ua + 8);
                    float f2 = __ldg(ua + 4 * 64);
                    float f3 = __ldg(ua + 4 * 64 + 8);
                    CVT_TF32(afr[ks][0], f0);
                    CVT_TF32(afr[ks][1], f1);
                    CVT_TF32(afr[ks][2], f2);
                    CVT_TF32(afr[ks][3], f3);
                }

                float m0[4][4];
                #pragma unroll
                for (int nq = 0; nq < 4; ++nq)
                    #pragma unroll
                    for (int q = 0; q < 4; ++q) m0[nq][q] = 0.f;

                #pragma unroll
                for (int ks = 0; ks < 4; ++ks) {
                    const float* vk = vb + (ks * 8 + tig) * 72 + gid;
                    #pragma unroll
                    for (int nq = 0; nq < 4; ++nq) {
                        const float* vp = vk + (ng * 4 + nq) * 8;
                        unsigned bfr[2];
                        float b0f = vp[0];
                        float b1f = vp[4 * 72];
                        CVT_TF32(bfr[0], b0f);
                        CVT_TF32(bfr[1], b1f);
                        MMA_TF32(m0[nq], afr[ks], bfr);
                    }
                }

                // ---- fold M into oacc with A^T coefficients ----
                const float CJ0[4] = {1.f, 1.f, 1.f, 0.f};
                const float CJ1[4] = {0.f, 1.f, -1.f, -1.f};
                #pragma unroll
                for (int r = 0; r < 2; ++r) {
                    float rcv = r ? a1i : a0i;
                    #pragma unroll
                    for (int c = 0; c < 2; ++c) {
                        float cj = c ? CJ1[jj] : CJ0[jj];
                        if (cj == 0.f) continue;     // compile-time prune
                        float coef = rcv * cj;
                        #pragma unroll
                        for (int nq = 0; nq < 4; ++nq)
                            #pragma unroll
                            for (int q = 0; q < 4; ++q)
                                oacc[r * 2 + c][nq][q] =
                                    fmaf(coef, m0[nq][q], oacc[r * 2 + c][nq][q]);
                    }
                }
            }
            __syncthreads();            // all GEMM reads of v_s done
        }
    }

    // ---- writeback: coalesced float4 per (co, y) ----
    // c-frag: creg q = 2h + d: row co0+gid+8h, col t = ni*8 + 2*tig + d
    // out pixel: y = th0 + ni*2 + r, x = tw0 + 4*tig + 2*d + c
    float* outp = g_co + (size_t)(sub * 8 + b) * 64 * 4096;
    #pragma unroll
    for (int h = 0; h < 2; ++h) {
        int co = co0 + gid + 8 * h;
        #pragma unroll
        for (int nq = 0; nq < 4; ++nq) {
            int ni = ng * 4 + nq;
            #pragma unroll
            for (int r = 0; r < 2; ++r) {
                float4 val = make_float4(
                    oacc[r * 2 + 0][nq][2 * h + 0],
                    oacc[r * 2 + 1][nq][2 * h + 0],
                    oacc[r * 2 + 0][nq][2 * h + 1],
                    oacc[r * 2 + 1][nq][2 * h + 1]);
                *(float4*)(outp + (size_t)co * 4096
                           + (size_t)(th0 + ni * 2 + r) * 64
                           + tw0 + 4 * tig) = val;
            }
        }
    }
}

// ---------------------------------------------------------------------------
// Kernel 4: inverse Haar DWT -> final output
// ---------------------------------------------------------------------------
__global__ void idwt_kernel(float* __restrict__ out) {
    int idx = blockIdx.x * blockDim.x + threadIdx.x;
    if (idx >= SB_STRIDE) return;
    int w  = idx & 63;
    int h  = (idx >> 6) & 63;
    int bc = idx >> 12;

    float ll = g_co[idx];
    float h0 = g_co[SB_STRIDE + idx];
    float h1 = g_co[2 * SB_STRIDE + idx];
    float hh = g_co[3 * SB_STRIDE + idx];

    float a  = (ll + h0 + h1 + hh) * 0.5f;
    float b_ = (ll + h0 - h1 - hh) * 0.5f;
    float c_ = (ll - h0 + h1 - hh) * 0.5f;
    float d_ = (ll - h0 - h1 + hh) * 0.5f;

    float2* top = (float2*)(out + ((size_t)bc * 128 + 2 * h) * 128);
    float2* bot = (float2*)(out + ((size_t)bc * 128 + 2 * h + 1) * 128);
    top[w] = make_float2(a, b_);
    bot[w] = make_float2(c_, d_);
}

// ---------------------------------------------------------------------------
// Launch
// ---------------------------------------------------------------------------
extern "C" void kernel_launch(void* const* d_in, const int* in_sizes, int n_in,
                              void* d_out, int out_size) {
    const float* x  = (const float*)d_in[0];
    const float* wt = (const float*)d_in[1];
    const float* aw = (const float*)d_in[2];
    const float* ab = (const float*)d_in[3];
    float* out = (float*)d_out;

    static const int kConvSmem = (10368 + 4 * 2304) * 4;   // 78336 B
    cudaFuncSetAttribute(wino_conv,
                         cudaFuncAttributeMaxDynamicSharedMemorySize, kConvSmem);

    dwt_kernel<<<NBC, 256>>>(x);
    attn_kernel<<<1, 32>>>(aw, ab);
    wino_mix<<<dim3(16, 4, 8), 256>>>(wt);
    wino_conv<<<dim3(16, 4, 8), 256, kConvSmem>>>();
    idwt_kernel<<<8192, 256>>>(out);
}

// round 16
// speedup vs baseline: 1.7017x; 1.0554x over previous
#include <cuda_runtime.h>
#include <math.h>

typedef unsigned long long ull;

// ---------------------------------------------------------------------------
// Scratch (static device globals; no runtime allocation)
// ---------------------------------------------------------------------------
__device__ float g_sb[4 * 8 * 64 * 64 * 64];        // subbands [sub][b][c][64][64]
__device__ float g_co[4 * 8 * 64 * 64 * 64];        // conv outs [sub][b][co][64][64]
__device__ float g_sums[8 * 64 * 4];                // per (b,c,sub) sums
__device__ float g_att[8 * 4 * 4];                  // attention [b][sub][k]
// Winograd U, PRE-ROUNDED to tf32 bit pattern: [b][sub][t][ci][co]
__device__ unsigned g_mku[8 * 4 * 16 * 64 * 64];

#define SB_STRIDE  2097152
#define NBC        512

// Winograd constant tables (B^T row/col selectors on pitch-18 rows, A^T coeffs)
__constant__ int   c_ra[4] = {0 * 18, 1 * 18, 2 * 18, 1 * 18};
__constant__ int   c_rb[4] = {2 * 18, 2 * 18, 1 * 18, 3 * 18};
__constant__ float c_rs[4] = {-1.f, 1.f, -1.f, -1.f};
__constant__ float c_A0[4] = {1.f, 1.f, 1.f, 0.f};   // A^T row 0
__constant__ float c_A1[4] = {0.f, 1.f, -1.f, -1.f}; // A^T row 1

#define CVT_TF32(d, s) asm("cvt.rna.tf32.f32 %0, %1;" : "=r"(d) : "f"(s))

#define MMA_TF32(d, a, b)                                                    \
    asm volatile(                                                            \
        "mma.sync.aligned.m16n8k8.row.col.f32.tf32.tf32.f32 "                \
        "{%0,%1,%2,%3}, {%4,%5,%6,%7}, {%8,%9}, {%0,%1,%2,%3};"              \
        : "+f"((d)[0]), "+f"((d)[1]), "+f"((d)[2]), "+f"((d)[3])             \
        : "r"((a)[0]), "r"((a)[1]), "r"((a)[2]), "r"((a)[3]),                \
          "r"((b)[0]), "r"((b)[1]))

// ---------------------------------------------------------------------------
// Kernel 1: Haar DWT fused with per-(b,c) subband sums
// ---------------------------------------------------------------------------
__global__ void dwt_kernel(const float* __restrict__ x) {
    int bc  = blockIdx.x;
    int tid = threadIdx.x;
    int ow  = tid & 63;
    int oh0 = tid >> 6;
    const float* xp = x + (size_t)bc * 128 * 128;

    float s0 = 0.f, s1 = 0.f, s2 = 0.f, s3 = 0.f;
    #pragma unroll 4
    for (int it = 0; it < 16; ++it) {
        int oh = oh0 + it * 4;
        float2 t  = ((const float2*)(xp + (2 * oh)     * 128))[ow];
        float2 bo = ((const float2*)(xp + (2 * oh + 1) * 128))[ow];
        float a = t.x, b_ = t.y, c_ = bo.x, d_ = bo.y;
        float ll = (a + b_ + c_ + d_) * 0.5f;
        float h0 = (a + b_ - c_ - d_) * 0.5f;
        float h1 = (a - b_ + c_ - d_) * 0.5f;
        float hh = (a - b_ - c_ + d_) * 0.5f;
        int o = bc * 4096 + oh * 64 + ow;
        g_sb[0 * SB_STRIDE + o] = ll;
        g_sb[1 * SB_STRIDE + o] = h0;
        g_sb[2 * SB_STRIDE + o] = h1;
        g_sb[3 * SB_STRIDE + o] = hh;
        s0 += ll; s1 += h0; s2 += h1; s3 += hh;
    }

    #pragma unroll
    for (int off = 16; off; off >>= 1) {
        s0 += __shfl_down_sync(0xffffffffu, s0, off);
        s1 += __shfl_down_sync(0xffffffffu, s1, off);
        s2 += __shfl_down_sync(0xffffffffu, s2, off);
        s3 += __shfl_down_sync(0xffffffffu, s3, off);
    }
    __shared__ float red[8][4];
    int warp = tid >> 5, lane = tid & 31;
    if (lane == 0) {
        red[warp][0] = s0; red[warp][1] = s1;
        red[warp][2] = s2; red[warp][3] = s3;
    }
    __syncthreads();
    if (tid < 4) {
        float s = 0.f;
        #pragma unroll
        for (int w = 0; w < 8; ++w) s += red[w][tid];
        g_sums[bc * 4 + tid] = s;
    }
}

// ---------------------------------------------------------------------------
// Kernel 2a: attention logits + softmax
// ---------------------------------------------------------------------------
__global__ void attn_kernel(const float* __restrict__ attn_w,
                            const float* __restrict__ attn_b) {
    int t = threadIdx.x;
    if (t >= 32) return;
    int b = t >> 2, i = t & 3;
    float logits[4];
    #pragma unroll
    for (int k = 0; k < 4; ++k) {
        float acc = 0.f;
        for (int c = 0; c < 64; ++c)
            acc += attn_w[k * 64 + c] * g_sums[(b * 64 + c) * 4 + i];
        logits[k] = acc * (1.0f / 4096.0f) + attn_b[k];
    }
    float m = fmaxf(fmaxf(logits[0], logits[1]), fmaxf(logits[2], logits[3]));
    float e[4]; float s = 0.f;
    #pragma unroll
    for (int k = 0; k < 4; ++k) { e[k] = expf(logits[k] - m); s += e[k]; }
    float inv = 1.0f / s;
    #pragma unroll
    for (int k = 0; k < 4; ++k) g_att[(b * 4 + i) * 4 + k] = e[k] * inv;
}

// ---------------------------------------------------------------------------
// Kernel 2b: mix kernels with attention AND transform to Winograd U,
// stored PRE-ROUNDED to tf32 (cvt once per value at production).
// ---------------------------------------------------------------------------
__global__ void wino_mix(const float* __restrict__ wt) {
    int cig = blockIdx.x, i = blockIdx.y, b = blockIdx.z;
    int bi = b * 4 + i;
    __shared__ float s[36 * 65];

    int tid = threadIdx.x;
    int co  = tid & 63;
    int cil = tid >> 6;

    float g9[9];
    #pragma unroll
    for (int q = 0; q < 9; ++q) g9[q] = 0.f;

    #pragma unroll
    for (int k = 0; k < 4; ++k) {
        float ak = g_att[bi * 4 + k];
        const float* src = wt + ((size_t)(k * 4 + i) * 64) * 576 + cig * 36;
        __syncthreads();
        for (int idx = tid; idx < 64 * 36; idx += 256) {
            int c = idx / 36;
            int j = idx - c * 36;
            s[j * 65 + c] = src[(size_t)c * 576 + j];
        }
        __syncthreads();
        #pragma unroll
        for (int q = 0; q < 9; ++q)
            g9[q] += ak * s[(cil * 9 + q) * 65 + co];
    }

    // U = G g G^T ; G = [[1,0,0],[.5,.5,.5],[.5,-.5,.5],[0,0,1]]
    float T[4][3];
    #pragma unroll
    for (int c = 0; c < 3; ++c) {
        float a = g9[c], bb = g9[3 + c], cc = g9[6 + c];
        T[0][c] = a;
        T[1][c] = 0.5f * (a + bb + cc);
        T[2][c] = 0.5f * (a - bb + cc);
        T[3][c] = cc;
    }
    unsigned* dst = g_mku + ((size_t)bi * 16) * 4096 + (cig * 4 + cil) * 64 + co;
    #pragma unroll
    for (int r = 0; r < 4; ++r) {
        float u0 = T[r][0], u1b = T[r][1], u2 = T[r][2];
        float U0 = u0;
        float U1 = 0.5f * (u0 + u1b + u2);
        float U2 = 0.5f * (u0 - u1b + u2);
        float U3 = u2;
        unsigned t0, t1, t2, t3;
        CVT_TF32(t0, U0); CVT_TF32(t1, U1);
        CVT_TF32(t2, U2); CVT_TF32(t3, U3);
        dst[(r * 4 + 0) * 4096] = t0;
        dst[(r * 4 + 1) * 4096] = t1;
        dst[(r * 4 + 2) * 4096] = t2;
        dst[(r * 4 + 3) * 4096] = t3;
    }
}

// ---------------------------------------------------------------------------
// Kernel 3: fused Winograd F(2x2,3x3) conv — tf32 mma.sync, CVT-FREE GEMM.
// Block = 256 threads (8 warps), 64 cout x 16x16 px (64 wino tiles), 1 (b,sub).
// V stored in v_s ALREADY tf32-rounded (cvt in transform, once per value).
// U loaded from g_mku already tf32-rounded. GEMM: pure LDG/LDS + MMA + fold.
// ---------------------------------------------------------------------------
__global__ void __launch_bounds__(256, 2) wino_conv() {
    extern __shared__ float sm[];
    float*    raw_s = sm;                 // 32*324 = 10368 floats
    unsigned* v_s   = (unsigned*)(sm + 10368);  // 4 jj x (32 ci x 72) tf32 bits

    int b   = blockIdx.z;
    int sub = blockIdx.y;
    int tb  = blockIdx.x;               // 0..15
    int th0 = (tb >> 2) * 16;           // output row origin (16 rows)
    int tw0 = (tb & 3) * 16;            // output col origin (16 cols)
    int bi  = b * 4 + sub;

    int tid  = threadIdx.x;
    int w    = tid >> 5;
    int lane = tid & 31;
    int gid  = lane >> 2;               // 0..7
    int tig  = lane & 3;                // 0..3
    int mi   = w & 3;                   // m-tile: co range mi*16..+16
    int ng   = w >> 2;                  // n-group (0 or 1)
    int co0  = mi * 16;

    const float*    sbp   = g_sb  + (size_t)(sub * 8 + b) * 64 * 4096;
    const unsigned* ubase = g_mku + (size_t)bi * 16 * 4096;

    // oacc[rc = r*2+c][nq][creg]: 4 x 4 x 4 fp32
    float oacc[4][4][4];
    #pragma unroll
    for (int rc = 0; rc < 4; ++rc)
        #pragma unroll
        for (int nq = 0; nq < 4; ++nq)
            #pragma unroll
            for (int q = 0; q < 4; ++q) oacc[rc][nq][q] = 0.f;

    for (int cich = 0; cich < 2; ++cich) {
        int cibase = cich * 32;

        // ---- stage raw halo: 32 ci x 18 x 18 (zero padded) ----
        for (int idx = tid; idx < 10368; idx += 256) {
            int ci  = idx / 324;
            int rem = idx - ci * 324;
            int y   = rem / 18;
            int xx  = rem - y * 18;
            int ih  = th0 - 1 + y;
            int iw  = tw0 - 1 + xx;
            float v = 0.f;
            if ((unsigned)ih < 64u && (unsigned)iw < 64u)
                v = sbp[(cibase + ci) * 4096 + ih * 64 + iw];
            raw_s[idx] = v;
        }
        __syncthreads();                // raw_s visible

        for (int ig = 0; ig < 4; ++ig) {
            int   ra = c_ra[ig];
            int   rb = c_rb[ig];
            float rs = c_rs[ig];

            // ---- transform: V[ig][jj=0..3], tf32-rounded at store ----
            #pragma unroll
            for (int q = 0; q < 8; ++q) {
                int idx = tid + q * 256;    // 2048 cells
                int ci  = idx >> 6;
                int tl  = idx & 63;
                const float* dp =
                    &raw_s[ci * 324 + (tl >> 3) * 36 + (tl & 7) * 2];
                float2 A0 = *(const float2*)(dp + ra);
                float2 A1 = *(const float2*)(dp + ra + 2);
                float2 B0 = *(const float2*)(dp + rb);
                float2 B1 = *(const float2*)(dp + rb + 2);
                float w0 = fmaf(rs, B0.x, A0.x);
                float w1 = fmaf(rs, B0.y, A0.y);
                float w2 = fmaf(rs, B1.x, A1.x);
                float w3 = fmaf(rs, B1.y, A1.y);
                float v0 = w0 - w2;
                float v1 = w1 + w2;
                float v2 = w2 - w1;
                float v3 = w1 - w3;
                unsigned p0, p1, p2, p3;
                CVT_TF32(p0, v0); CVT_TF32(p1, v1);
                CVT_TF32(p2, v2); CVT_TF32(p3, v3);
                int off = ci * 72 + tl;
                v_s[0 * 2304 + off] = p0;
                v_s[1 * 2304 + off] = p1;
                v_s[2 * 2304 + off] = p2;
                v_s[3 * 2304 + off] = p3;
            }
            __syncthreads();            // v_s visible

            float a0i = c_A0[ig], a1i = c_A1[ig];

            #pragma unroll 1
            for (int jj = 0; jj < 4; ++jj) {    // sync-free GEMM stretch
                const unsigned* vb = v_s + jj * 2304;
                const unsigned* gu = ubase + (size_t)(ig * 4 + jj) * 4096
                                     + cibase * 64;

                // ---- A fragments: 16 upfront LDGs, NO cvt ----
                unsigned afr[4][4];
                #pragma unroll
                for (int ks = 0; ks < 4; ++ks) {
                    const unsigned* ua = gu + (ks * 8 + tig) * 64 + co0 + gid;
                    afr[ks][0] = __ldg(ua);
                    afr[ks][1] = __ldg(ua + 8);
                    afr[ks][2] = __ldg(ua + 4 * 64);
                    afr[ks][3] = __ldg(ua + 4 * 64 + 8);
                }

                float m0[4][4];
                #pragma unroll
                for (int nq = 0; nq < 4; ++nq)
                    #pragma unroll
                    for (int q = 0; q < 4; ++q) m0[nq][q] = 0.f;

                #pragma unroll
                for (int ks = 0; ks < 4; ++ks) {
                    const unsigned* vk = vb + (ks * 8 + tig) * 72 + gid;
                    #pragma unroll
                    for (int nq = 0; nq < 4; ++nq) {
                        const unsigned* vp = vk + (ng * 4 + nq) * 8;
                        unsigned bfr[2];
                        bfr[0] = vp[0];
                        bfr[1] = vp[4 * 72];
                        MMA_TF32(m0[nq], afr[ks], bfr);
                    }
                }

                // ---- fold M into oacc with A^T coefficients ----
                const float CJ0[4] = {1.f, 1.f, 1.f, 0.f};
                const float CJ1[4] = {0.f, 1.f, -1.f, -1.f};
                #pragma unroll
                for (int r = 0; r < 2; ++r) {
                    float rcv = r ? a1i : a0i;
                    #pragma unroll
                    for (int c = 0; c < 2; ++c) {
                        float cj = c ? CJ1[jj] : CJ0[jj];
                        if (cj == 0.f) continue;     // compile-time prune
                        float coef = rcv * cj;
                        #pragma unroll
                        for (int nq = 0; nq < 4; ++nq)
                            #pragma unroll
                            for (int q = 0; q < 4; ++q)
                                oacc[r * 2 + c][nq][q] =
                                    fmaf(coef, m0[nq][q], oacc[r * 2 + c][nq][q]);
                    }
                }
            }
            __syncthreads();            // all GEMM reads of v_s done
        }
    }

    // ---- writeback: coalesced float4 per (co, y) ----
    float* outp = g_co + (size_t)(sub * 8 + b) * 64 * 4096;
    #pragma unroll
    for (int h = 0; h < 2; ++h) {
        int co = co0 + gid + 8 * h;
        #pragma unroll
        for (int nq = 0; nq < 4; ++nq) {
            int ni = ng * 4 + nq;
            #pragma unroll
            for (int r = 0; r < 2; ++r) {
                float4 val = make_float4(
                    oacc[r * 2 + 0][nq][2 * h + 0],
                    oacc[r * 2 + 1][nq][2 * h + 0],
                    oacc[r * 2 + 0][nq][2 * h + 1],
                    oacc[r * 2 + 1][nq][2 * h + 1]);
                *(float4*)(outp + (size_t)co * 4096
                           + (size_t)(th0 + ni * 2 + r) * 64
                           + tw0 + 4 * tig) = val;
            }
        }
    }
}

// ---------------------------------------------------------------------------
// Kernel 4: inverse Haar DWT -> final output
// ---------------------------------------------------------------------------
__global__ void idwt_kernel(float* __restrict__ out) {
    int idx = blockIdx.x * blockDim.x + threadIdx.x;
    if (idx >= SB_STRIDE) return;
    int w  = idx & 63;
    int h  = (idx >> 6) & 63;
    int bc = idx >> 12;

    float ll = g_co[idx];
    float h0 = g_co[SB_STRIDE + idx];
    float h1 = g_co[2 * SB_STRIDE + idx];
    float hh = g_co[3 * SB_STRIDE + idx];

    float a  = (ll + h0 + h1 + hh) * 0.5f;
    float b_ = (ll + h0 - h1 - hh) * 0.5f;
    float c_ = (ll - h0 + h1 - hh) * 0.5f;
    float d_ = (ll - h0 - h1 + hh) * 0.5f;

    float2* top = (float2*)(out + ((size_t)bc * 128 + 2 * h) * 128);
    float2* bot = (float2*)(out + ((size_t)bc * 128 + 2 * h + 1) * 128);
    top[w] = make_float2(a, b_);
    bot[w] = make_float2(c_, d_);
}

// ---------------------------------------------------------------------------
// Launch
// ---------------------------------------------------------------------------
extern "C" void kernel_launch(void* const* d_in, const int* in_sizes, int n_in,
                              void* d_out, int out_size) {
    const float* x  = (const float*)d_in[0];
    const float* wt = (const float*)d_in[1];
    const float* aw = (const float*)d_in[2];
    const float* ab = (const float*)d_in[3];
    float* out = (float*)d_out;

    static const int kConvSmem = (10368 + 4 * 2304) * 4;   // 78336 B
    cudaFuncSetAttribute(wino_conv,
                         cudaFuncAttributeMaxDynamicSharedMemorySize, kConvSmem);

    dwt_kernel<<<NBC, 256>>>(x);
    attn_kernel<<<1, 32>>>(aw, ab);
    wino_mix<<<dim3(16, 4, 8), 256>>>(wt);
    wino_conv<<<dim3(16, 4, 8), 256, kConvSmem>>>();
    idwt_kernel<<<8192, 256>>>(out);
}

// round 17
// speedup vs baseline: 1.8249x; 1.0724x over previous
#include <cuda_runtime.h>
#include <math.h>

typedef unsigned long long ull;

// ---------------------------------------------------------------------------
// Scratch (static device globals; no runtime allocation)
// ---------------------------------------------------------------------------
__device__ float g_sb[4 * 8 * 64 * 64 * 64];        // subbands [sub][b][c][64][64]
__device__ float g_co[4 * 8 * 64 * 64 * 64];        // conv outs [sub][b][co][64][64]
__device__ float g_sums[8 * 64 * 4];                // per (b,c,sub) sums
__device__ float g_att[8 * 4 * 4];                  // attention [b][sub][k]
// Winograd U, PRE-ROUNDED to tf32 bit pattern: [b][sub][t][ci][co]
__device__ unsigned g_mku[8 * 4 * 16 * 64 * 64];

#define SB_STRIDE  2097152
#define NBC        512

// Winograd constant tables (B^T row/col selectors on pitch-18 rows, A^T coeffs)
__constant__ int   c_ra[4] = {0 * 18, 1 * 18, 2 * 18, 1 * 18};
__constant__ int   c_rb[4] = {2 * 18, 2 * 18, 1 * 18, 3 * 18};
__constant__ float c_rs[4] = {-1.f, 1.f, -1.f, -1.f};
__constant__ float c_A0[4] = {1.f, 1.f, 1.f, 0.f};   // A^T row 0
__constant__ float c_A1[4] = {0.f, 1.f, -1.f, -1.f}; // A^T row 1

#define CVT_TF32(d, s) asm("cvt.rna.tf32.f32 %0, %1;" : "=r"(d) : "f"(s))

#define MMA_TF32(d, a, b)                                                    \
    asm volatile(                                                            \
        "mma.sync.aligned.m16n8k8.row.col.f32.tf32.tf32.f32 "                \
        "{%0,%1,%2,%3}, {%4,%5,%6,%7}, {%8,%9}, {%0,%1,%2,%3};"              \
        : "+f"((d)[0]), "+f"((d)[1]), "+f"((d)[2]), "+f"((d)[3])             \
        : "r"((a)[0]), "r"((a)[1]), "r"((a)[2]), "r"((a)[3]),                \
          "r"((b)[0]), "r"((b)[1]))

// ---------------------------------------------------------------------------
// Kernel 1: Haar DWT fused with per-(b,c) subband sums
// ---------------------------------------------------------------------------
__global__ void dwt_kernel(const float* __restrict__ x) {
    int bc  = blockIdx.x;
    int tid = threadIdx.x;
    int ow  = tid & 63;
    int oh0 = tid >> 6;
    const float* xp = x + (size_t)bc * 128 * 128;

    float s0 = 0.f, s1 = 0.f, s2 = 0.f, s3 = 0.f;
    #pragma unroll 4
    for (int it = 0; it < 16; ++it) {
        int oh = oh0 + it * 4;
        float2 t  = ((const float2*)(xp + (2 * oh)     * 128))[ow];
        float2 bo = ((const float2*)(xp + (2 * oh + 1) * 128))[ow];
        float a = t.x, b_ = t.y, c_ = bo.x, d_ = bo.y;
        float ll = (a + b_ + c_ + d_) * 0.5f;
        float h0 = (a + b_ - c_ - d_) * 0.5f;
        float h1 = (a - b_ + c_ - d_) * 0.5f;
        float hh = (a - b_ - c_ + d_) * 0.5f;
        int o = bc * 4096 + oh * 64 + ow;
        g_sb[0 * SB_STRIDE + o] = ll;
        g_sb[1 * SB_STRIDE + o] = h0;
        g_sb[2 * SB_STRIDE + o] = h1;
        g_sb[3 * SB_STRIDE + o] = hh;
        s0 += ll; s1 += h0; s2 += h1; s3 += hh;
    }

    #pragma unroll
    for (int off = 16; off; off >>= 1) {
        s0 += __shfl_down_sync(0xffffffffu, s0, off);
        s1 += __shfl_down_sync(0xffffffffu, s1, off);
        s2 += __shfl_down_sync(0xffffffffu, s2, off);
        s3 += __shfl_down_sync(0xffffffffu, s3, off);
    }
    __shared__ float red[8][4];
    int warp = tid >> 5, lane = tid & 31;
    if (lane == 0) {
        red[warp][0] = s0; red[warp][1] = s1;
        red[warp][2] = s2; red[warp][3] = s3;
    }
    __syncthreads();
    if (tid < 4) {
        float s = 0.f;
        #pragma unroll
        for (int w = 0; w < 8; ++w) s += red[w][tid];
        g_sums[bc * 4 + tid] = s;
    }
}

// ---------------------------------------------------------------------------
// Kernel 2a: attention logits + softmax
// ---------------------------------------------------------------------------
__global__ void attn_kernel(const float* __restrict__ attn_w,
                            const float* __restrict__ attn_b) {
    int t = threadIdx.x;
    if (t >= 32) return;
    int b = t >> 2, i = t & 3;
    float logits[4];
    #pragma unroll
    for (int k = 0; k < 4; ++k) {
        float acc = 0.f;
        for (int c = 0; c < 64; ++c)
            acc += attn_w[k * 64 + c] * g_sums[(b * 64 + c) * 4 + i];
        logits[k] = acc * (1.0f / 4096.0f) + attn_b[k];
    }
    float m = fmaxf(fmaxf(logits[0], logits[1]), fmaxf(logits[2], logits[3]));
    float e[4]; float s = 0.f;
    #pragma unroll
    for (int k = 0; k < 4; ++k) { e[k] = expf(logits[k] - m); s += e[k]; }
    float inv = 1.0f / s;
    #pragma unroll
    for (int k = 0; k < 4; ++k) g_att[(b * 4 + i) * 4 + k] = e[k] * inv;
}

// ---------------------------------------------------------------------------
// Kernel 2b: mix kernels with attention AND transform to Winograd U,
// stored PRE-ROUNDED to tf32 (cvt once per value at production).
// ---------------------------------------------------------------------------
__global__ void wino_mix(const float* __restrict__ wt) {
    int cig = blockIdx.x, i = blockIdx.y, b = blockIdx.z;
    int bi = b * 4 + i;
    __shared__ float s[36 * 65];

    int tid = threadIdx.x;
    int co  = tid & 63;
    int cil = tid >> 6;

    float g9[9];
    #pragma unroll
    for (int q = 0; q < 9; ++q) g9[q] = 0.f;

    #pragma unroll
    for (int k = 0; k < 4; ++k) {
        float ak = g_att[bi * 4 + k];
        const float* src = wt + ((size_t)(k * 4 + i) * 64) * 576 + cig * 36;
        __syncthreads();
        for (int idx = tid; idx < 64 * 36; idx += 256) {
            int c = idx / 36;
            int j = idx - c * 36;
            s[j * 65 + c] = src[(size_t)c * 576 + j];
        }
        __syncthreads();
        #pragma unroll
        for (int q = 0; q < 9; ++q)
            g9[q] += ak * s[(cil * 9 + q) * 65 + co];
    }

    // U = G g G^T ; G = [[1,0,0],[.5,.5,.5],[.5,-.5,.5],[0,0,1]]
    float T[4][3];
    #pragma unroll
    for (int c = 0; c < 3; ++c) {
        float a = g9[c], bb = g9[3 + c], cc = g9[6 + c];
        T[0][c] = a;
        T[1][c] = 0.5f * (a + bb + cc);
        T[2][c] = 0.5f * (a - bb + cc);
        T[3][c] = cc;
    }
    unsigned* dst = g_mku + ((size_t)bi * 16) * 4096 + (cig * 4 + cil) * 64 + co;
    #pragma unroll
    for (int r = 0; r < 4; ++r) {
        float u0 = T[r][0], u1b = T[r][1], u2 = T[r][2];
        float U0 = u0;
        float U1 = 0.5f * (u0 + u1b + u2);
        float U2 = 0.5f * (u0 - u1b + u2);
        float U3 = u2;
        unsigned t0, t1, t2, t3;
        CVT_TF32(t0, U0); CVT_TF32(t1, U1);
        CVT_TF32(t2, U2); CVT_TF32(t3, U3);
        dst[(r * 4 + 0) * 4096] = t0;
        dst[(r * 4 + 1) * 4096] = t1;
        dst[(r * 4 + 2) * 4096] = t2;
        dst[(r * 4 + 3) * 4096] = t3;
    }
}

// ---------------------------------------------------------------------------
// Kernel 3: fused Winograd F(2x2,3x3) conv — tf32 mma.sync, U VIA SMEM.
// Block = 256 threads (8 warps), 64 cout x 16x16 px (64 wino tiles), 1 (b,sub).
// V (tf32-rounded) in v_s pitch 72; U double-buffered in u_s pitch 72
// (banks 8*tig+gid: conflict-free A-frag LDS).  Stage U(ig,0) with the
// transform; stage U(ig,jj+1) during GEMM jj -> block-amortized L2 latency.
// ---------------------------------------------------------------------------
__global__ void __launch_bounds__(256, 2) wino_conv() {
    extern __shared__ float sm[];
    float*    raw_s = sm;                          // 10368 floats
    unsigned* v_s   = (unsigned*)(sm + 10368);     // 4 jj x (32 x 72)  = 9216
    unsigned* u_s   = (unsigned*)(sm + 10368 + 9216);  // 2 x (32 x 72) = 4608

    int b   = blockIdx.z;
    int sub = blockIdx.y;
    int tb  = blockIdx.x;               // 0..15
    int th0 = (tb >> 2) * 16;           // output row origin (16 rows)
    int tw0 = (tb & 3) * 16;            // output col origin (16 cols)
    int bi  = b * 4 + sub;

    int tid  = threadIdx.x;
    int w    = tid >> 5;
    int lane = tid & 31;
    int gid  = lane >> 2;               // 0..7
    int tig  = lane & 3;                // 0..3
    int mi   = w & 3;                   // m-tile: co range mi*16..+16
    int ng   = w >> 2;                  // n-group (0 or 1)
    int co0  = mi * 16;

    const float*    sbp   = g_sb  + (size_t)(sub * 8 + b) * 64 * 4096;
    const unsigned* ubase = g_mku + (size_t)bi * 16 * 4096;

    // stage-U lambda replacement (macro-ish): row = idx4>>4, col4 = (idx4&15)*4
    // src pitch 64 (global), dst pitch 72 (smem); 2 float4 per thread.
#define STAGE_U(dstbuf, guofs)                                               \
    do {                                                                     \
        const float4* usrc4 = (const float4*)(ubase + (guofs));              \
        unsigned* ud = (dstbuf);                                             \
        _Pragma("unroll")                                                    \
        for (int q = 0; q < 2; ++q) {                                        \
            int idx4 = tid + q * 256;                                        \
            int row  = idx4 >> 4;                                            \
            int col4 = (idx4 & 15) << 2;                                     \
            float4 val = usrc4[idx4];                                        \
            *(float4*)(ud + row * 72 + col4) = val;                          \
        }                                                                    \
    } while (0)

    // oacc[rc = r*2+c][nq][creg]: 4 x 4 x 4 fp32
    float oacc[4][4][4];
    #pragma unroll
    for (int rc = 0; rc < 4; ++rc)
        #pragma unroll
        for (int nq = 0; nq < 4; ++nq)
            #pragma unroll
            for (int q = 0; q < 4; ++q) oacc[rc][nq][q] = 0.f;

    for (int cich = 0; cich < 2; ++cich) {
        int cibase = cich * 32;

        // ---- stage raw halo: 32 ci x 18 x 18 (zero padded) ----
        for (int idx = tid; idx < 10368; idx += 256) {
            int ci  = idx / 324;
            int rem = idx - ci * 324;
            int y   = rem / 18;
            int xx  = rem - y * 18;
            int ih  = th0 - 1 + y;
            int iw  = tw0 - 1 + xx;
            float v = 0.f;
            if ((unsigned)ih < 64u && (unsigned)iw < 64u)
                v = sbp[(cibase + ci) * 4096 + ih * 64 + iw];
            raw_s[idx] = v;
        }
        __syncthreads();                // raw_s visible

        for (int ig = 0; ig < 4; ++ig) {
            int   ra = c_ra[ig];
            int   rb = c_rb[ig];
            float rs = c_rs[ig];

            // ---- transform: V[ig][jj=0..3], tf32-rounded at store ----
            #pragma unroll
            for (int q = 0; q < 8; ++q) {
                int idx = tid + q * 256;    // 2048 cells
                int ci  = idx >> 6;
                int tl  = idx & 63;
                const float* dp =
                    &raw_s[ci * 324 + (tl >> 3) * 36 + (tl & 7) * 2];
                float2 A0 = *(const float2*)(dp + ra);
                float2 A1 = *(const float2*)(dp + ra + 2);
                float2 B0 = *(const float2*)(dp + rb);
                float2 B1 = *(const float2*)(dp + rb + 2);
                float w0 = fmaf(rs, B0.x, A0.x);
                float w1 = fmaf(rs, B0.y, A0.y);
                float w2 = fmaf(rs, B1.x, A1.x);
                float w3 = fmaf(rs, B1.y, A1.y);
                float v0 = w0 - w2;
                float v1 = w1 + w2;
                float v2 = w2 - w1;
                float v3 = w1 - w3;
                unsigned p0, p1, p2, p3;
                CVT_TF32(p0, v0); CVT_TF32(p1, v1);
                CVT_TF32(p2, v2); CVT_TF32(p3, v3);
                int off = ci * 72 + tl;
                v_s[0 * 2304 + off] = p0;
                v_s[1 * 2304 + off] = p1;
                v_s[2 * 2304 + off] = p2;
                v_s[3 * 2304 + off] = p3;
            }

            // ---- stage U(ig,0) into buffer 0 (overlaps transform) ----
            STAGE_U(u_s, (size_t)(ig * 4) * 4096 + cibase * 64);
            __syncthreads();            // v_s + u_s[0] visible

            float a0i = c_A0[ig], a1i = c_A1[ig];

            #pragma unroll 1
            for (int jj = 0; jj < 4; ++jj) {
                const unsigned* vb = v_s + jj * 2304;
                const unsigned* ub = u_s + (jj & 1) * 2304;

                // ---- A fragments: 16 LDS (29cyc, conflict-free) ----
                unsigned afr[4][4];
                #pragma unroll
                for (int ks = 0; ks < 4; ++ks) {
                    const unsigned* ua = ub + (ks * 8 + tig) * 72 + co0 + gid;
                    afr[ks][0] = ua[0];
                    afr[ks][1] = ua[8];
                    afr[ks][2] = ua[4 * 72];
                    afr[ks][3] = ua[4 * 72 + 8];
                }

                float m0[4][4];
                #pragma unroll
                for (int nq = 0; nq < 4; ++nq)
                    #pragma unroll
                    for (int q = 0; q < 4; ++q) m0[nq][q] = 0.f;

                #pragma unroll
                for (int ks = 0; ks < 4; ++ks) {
                    const unsigned* vk = vb + (ks * 8 + tig) * 72 + gid;
                    #pragma unroll
                    for (int nq = 0; nq < 4; ++nq) {
                        const unsigned* vp = vk + (ng * 4 + nq) * 8;
                        unsigned bfr[2];
                        bfr[0] = vp[0];
                        bfr[1] = vp[4 * 72];
                        MMA_TF32(m0[nq], afr[ks], bfr);
                    }
                }

                // ---- stage U(ig,jj+1) into other buffer (hidden by fold) ----
                if (jj < 3)
                    STAGE_U(u_s + ((jj + 1) & 1) * 2304,
                            (size_t)(ig * 4 + jj + 1) * 4096 + cibase * 64);

                // ---- fold M into oacc with A^T coefficients ----
                const float CJ0[4] = {1.f, 1.f, 1.f, 0.f};
                const float CJ1[4] = {0.f, 1.f, -1.f, -1.f};
                #pragma unroll
                for (int r = 0; r < 2; ++r) {
                    float rcv = r ? a1i : a0i;
                    #pragma unroll
                    for (int c = 0; c < 2; ++c) {
                        float cj = c ? CJ1[jj] : CJ0[jj];
                        if (cj == 0.f) continue;     // compile-time prune
                        float coef = rcv * cj;
                        #pragma unroll
                        for (int nq = 0; nq < 4; ++nq)
                            #pragma unroll
                            for (int q = 0; q < 4; ++q)
                                oacc[r * 2 + c][nq][q] =
                                    fmaf(coef, m0[nq][q], oacc[r * 2 + c][nq][q]);
                    }
                }
                __syncthreads();        // staged buffer visible; GEMM reads done
            }
        }
    }

    // ---- writeback: coalesced float4 per (co, y) ----
    float* outp = g_co + (size_t)(sub * 8 + b) * 64 * 4096;
    #pragma unroll
    for (int h = 0; h < 2; ++h) {
        int co = co0 + gid + 8 * h;
        #pragma unroll
        for (int nq = 0; nq < 4; ++nq) {
            int ni = ng * 4 + nq;
            #pragma unroll
            for (int r = 0; r < 2; ++r) {
                float4 val = make_float4(
                    oacc[r * 2 + 0][nq][2 * h + 0],
                    oacc[r * 2 + 1][nq][2 * h + 0],
                    oacc[r * 2 + 0][nq][2 * h + 1],
                    oacc[r * 2 + 1][nq][2 * h + 1]);
                *(float4*)(outp + (size_t)co * 4096
                           + (size_t)(th0 + ni * 2 + r) * 64
                           + tw0 + 4 * tig) = val;
            }
        }
    }
#undef STAGE_U
}

// ---------------------------------------------------------------------------
// Kernel 4: inverse Haar DWT -> final output
// ---------------------------------------------------------------------------
__global__ void idwt_kernel(float* __restrict__ out) {
    int idx = blockIdx.x * blockDim.x + threadIdx.x;
    if (idx >= SB_STRIDE) return;
    int w  = idx & 63;
    int h  = (idx >> 6) & 63;
    int bc = idx >> 12;

    float ll = g_co[idx];
    float h0 = g_co[SB_STRIDE + idx];
    float h1 = g_co[2 * SB_STRIDE + idx];
    float hh = g_co[3 * SB_STRIDE + idx];

    float a  = (ll + h0 + h1 + hh) * 0.5f;
    float b_ = (ll + h0 - h1 - hh) * 0.5f;
    float c_ = (ll - h0 + h1 - hh) * 0.5f;
    float d_ = (ll - h0 - h1 + hh) * 0.5f;

    float2* top = (float2*)(out + ((size_t)bc * 128 + 2 * h) * 128);
    float2* bot = (float2*)(out + ((size_t)bc * 128 + 2 * h + 1) * 128);
    top[w] = make_float2(a, b_);
    bot[w] = make_float2(c_, d_);
}

// ---------------------------------------------------------------------------
// Launch
// ---------------------------------------------------------------------------
extern "C" void kernel_launch(void* const* d_in, const int* in_sizes, int n_in,
                              void* d_out, int out_size) {
    const float* x  = (const float*)d_in[0];
    const float* wt = (const float*)d_in[1];
    const float* aw = (const float*)d_in[2];
    const float* ab = (const float*)d_in[3];
    float* out = (float*)d_out;

    static const int kConvSmem = (10368 + 9216 + 4608) * 4;   // 96768 B
    cudaFuncSetAttribute(wino_conv,
                         cudaFuncAttributeMaxDynamicSharedMemorySize, kConvSmem);

    dwt_kernel<<<NBC, 256>>>(x);
    attn_kernel<<<1, 32>>>(aw, ab);
    wino_mix<<<dim3(16, 4, 8), 256>>>(wt);
    wino_conv<<<dim3(16, 4, 8), 256, kConvSmem>>>();
    idwt_kernel<<<8192, 256>>>(out);
}